// round 1
// baseline (speedup 1.0000x reference)
#include <cuda_runtime.h>
#include <math.h>

#define NB 8
#define NH 4
#define NN 1024
#define ND 512

// Scratch (static device globals — no allocation allowed in kernel_launch)
static __device__ float g_Y[(size_t)NB * NH * NN * ND];   //  67 MB: x @ W per (b,h)
static __device__ float g_S[(size_t)NB * NH * NN * NN];   // 134 MB: scaled bilinear logits
static __device__ float g_P[(size_t)NB * NN * NN];        //  33 MB: head-averaged softmax

// ---------------------------------------------------------------------------
// Classic fp32 SGEMM: 128x128 block tile, BK=8, 256 threads, 8x8 per thread.
// MODE 0: Y[z] = x_b @ W_h          (NN, M=1024 N=512  K=512)
// MODE 1: S[z] = a * Y[z] @ x_b^T   (NT, M=1024 N=1024 K=512)
// MODE 2: out_b = P_b @ x_b         (NN, M=1024 N=512  K=1024)
// ---------------------------------------------------------------------------
template <int MODE>
__global__ __launch_bounds__(256) void sgemm_kernel(const float* __restrict__ x,
                                                    const float* __restrict__ Wt,
                                                    float* __restrict__ out) {
    constexpr int BM = 128, BN = 128, BK = 8;

    const int z = blockIdx.z;
    const float* A;
    const float* Bm;
    float* C;
    int Ksz, lda, ldb, ldc;
    float alpha = 1.0f;

    if (MODE == 0) {
        const int b = z >> 2, h = z & 3;
        A = x + (size_t)b * NN * ND;
        Bm = Wt + (size_t)h * ND * ND;
        C = g_Y + (size_t)z * NN * ND;
        Ksz = ND; lda = ND; ldb = ND; ldc = ND;
    } else if (MODE == 1) {
        const int b = z >> 2;
        A = g_Y + (size_t)z * NN * ND;
        Bm = x + (size_t)b * NN * ND;     // B^T: rows of x_b
        C = g_S + (size_t)z * NN * NN;
        Ksz = ND; lda = ND; ldb = ND; ldc = NN;
        alpha = 0.04419417382415922f;     // 512^-0.5
    } else {
        A = g_P + (size_t)z * NN * NN;
        Bm = x + (size_t)z * NN * ND;
        C = out + (size_t)z * NN * ND;
        Ksz = NN; lda = NN; ldb = ND; ldc = ND;
    }

    const int mBase = blockIdx.y * BM;
    const int nBase = blockIdx.x * BN;
    const int t = threadIdx.x;

    __shared__ float As[BK][BM];
    __shared__ float Bs[BK][BN];

    float acc[8][8];
#pragma unroll
    for (int i = 0; i < 8; i++)
#pragma unroll
        for (int j = 0; j < 8; j++) acc[i][j] = 0.0f;

    // Load index maps
    const int aRow = t >> 1;            // 0..127
    const int aCol = (t & 1) * 4;       // 0 or 4
    const int bRowK = t >> 5;           // 0..7   (NN-layout B: K rows)
    const int bColK = (t & 31) * 4;     // 0..124 (NN-layout B: N cols)
    const int tr = (t >> 4) * 8;        // thread tile row base
    const int tc = (t & 15) * 8;        // thread tile col base

    for (int k0 = 0; k0 < Ksz; k0 += BK) {
        // A tile: BM x BK (row-major M x K), stored transposed in smem
        {
            float4 a4 = *(const float4*)(A + (size_t)(mBase + aRow) * lda + k0 + aCol);
            As[aCol + 0][aRow] = a4.x;
            As[aCol + 1][aRow] = a4.y;
            As[aCol + 2][aRow] = a4.z;
            As[aCol + 3][aRow] = a4.w;
        }
        // B tile
        if (MODE == 1) {
            // B^T path: B stored N x K row-major; tile = BN rows x BK cols
            float4 b4 = *(const float4*)(Bm + (size_t)(nBase + aRow) * ldb + k0 + aCol);
            Bs[aCol + 0][aRow] = b4.x;
            Bs[aCol + 1][aRow] = b4.y;
            Bs[aCol + 2][aRow] = b4.z;
            Bs[aCol + 3][aRow] = b4.w;
        } else {
            // NN path: B stored K x N row-major; tile = BK rows x BN cols
            float4 b4 = *(const float4*)(Bm + (size_t)(k0 + bRowK) * ldb + nBase + bColK);
            *(float4*)&Bs[bRowK][bColK] = b4;
        }
        __syncthreads();

#pragma unroll
        for (int kk = 0; kk < BK; kk++) {
            float ar[8], br[8];
            *(float4*)&ar[0] = *(const float4*)&As[kk][tr];
            *(float4*)&ar[4] = *(const float4*)&As[kk][tr + 4];
            *(float4*)&br[0] = *(const float4*)&Bs[kk][tc];
            *(float4*)&br[4] = *(const float4*)&Bs[kk][tc + 4];
#pragma unroll
            for (int i = 0; i < 8; i++)
#pragma unroll
                for (int j = 0; j < 8; j++) acc[i][j] = fmaf(ar[i], br[j], acc[i][j]);
        }
        __syncthreads();
    }

    // Epilogue
#pragma unroll
    for (int i = 0; i < 8; i++) {
        float* crow = C + (size_t)(mBase + tr + i) * ldc + nBase + tc;
        float4 c0, c1;
        c0.x = acc[i][0] * alpha; c0.y = acc[i][1] * alpha;
        c0.z = acc[i][2] * alpha; c0.w = acc[i][3] * alpha;
        c1.x = acc[i][4] * alpha; c1.y = acc[i][5] * alpha;
        c1.z = acc[i][6] * alpha; c1.w = acc[i][7] * alpha;
        *(float4*)crow = c0;
        *(float4*)(crow + 4) = c1;
    }
}

// ---------------------------------------------------------------------------
// K3: per-row softmax over 4 heads, averaged: Pavg[b,n,:] = mean_h softmax(S[b,h,n,:])
// One block per (b,n), 256 threads, 4 columns per thread (float4).
// ---------------------------------------------------------------------------
__global__ __launch_bounds__(256) void softmax_avg_kernel() {
    const int bn = blockIdx.x;
    const int b = bn >> 10;
    const int n = bn & (NN - 1);
    const int t = threadIdx.x;
    const int lane = t & 31;
    const int warp = t >> 5;

    __shared__ float sred[8];
    __shared__ float sval;

    float a0 = 0.f, a1 = 0.f, a2 = 0.f, a3 = 0.f;

#pragma unroll
    for (int h = 0; h < NH; h++) {
        const float* row = g_S + ((size_t)(b * NH + h) * NN + n) * NN;
        float4 v = *(const float4*)(row + t * 4);

        // row max
        float m = fmaxf(fmaxf(v.x, v.y), fmaxf(v.z, v.w));
#pragma unroll
        for (int o = 16; o; o >>= 1) m = fmaxf(m, __shfl_xor_sync(0xffffffffu, m, o));
        if (lane == 0) sred[warp] = m;
        __syncthreads();
        if (t == 0) {
            float mm = sred[0];
#pragma unroll
            for (int i = 1; i < 8; i++) mm = fmaxf(mm, sred[i]);
            sval = mm;
        }
        __syncthreads();
        m = sval;

        // exp + sum
        float e0 = expf(v.x - m), e1 = expf(v.y - m), e2 = expf(v.z - m), e3 = expf(v.w - m);
        float s = (e0 + e1) + (e2 + e3);
#pragma unroll
        for (int o = 16; o; o >>= 1) s += __shfl_xor_sync(0xffffffffu, s, o);
        if (lane == 0) sred[warp] = s;
        __syncthreads();
        if (t == 0) {
            float ss = 0.f;
#pragma unroll
            for (int i = 0; i < 8; i++) ss += sred[i];
            sval = ss;
        }
        __syncthreads();
        const float inv = 0.25f / sval;   // fold mean over H=4 heads

        a0 = fmaf(e0, inv, a0);
        a1 = fmaf(e1, inv, a1);
        a2 = fmaf(e2, inv, a2);
        a3 = fmaf(e3, inv, a3);
        // sred/sval reuse next iter is ordered by the syncthreads above
    }

    float4 o4;
    o4.x = a0; o4.y = a1; o4.z = a2; o4.w = a3;
    *(float4*)(g_P + ((size_t)b * NN + n) * NN + t * 4) = o4;
}

// ---------------------------------------------------------------------------
extern "C" void kernel_launch(void* const* d_in, const int* in_sizes, int n_in,
                              void* d_out, int out_size) {
    const float* x = (const float*)d_in[0];   // [8, 1024, 512]
    const float* W = (const float*)d_in[1];   // [4, 512, 512]
    float* out = (float*)d_out;               // [8, 1024, 512]
    (void)in_sizes; (void)n_in; (void)out_size;

    // K1: Y[b,h] = x_b @ W_h
    sgemm_kernel<0><<<dim3(ND / 128, NN / 128, NB * NH), 256>>>(x, W, out);
    // K2: S[b,h] = scale * Y[b,h] @ x_b^T
    sgemm_kernel<1><<<dim3(NN / 128, NN / 128, NB * NH), 256>>>(x, W, out);
    // K3: Pavg[b] = mean_h softmax_rows(S[b,h])
    softmax_avg_kernel<<<NB * NN, 256>>>();
    // K4: out_b = Pavg_b @ x_b
    sgemm_kernel<2><<<dim3(ND / 128, NN / 128, NB), 256>>>(x, W, out);
}

// round 15
// speedup vs baseline: 2.2792x; 2.2792x over previous
#include <cuda_runtime.h>
#include <cuda_fp16.h>
#include <cstdint>
#include <math.h>

#define NB 8
#define NH 4
#define NN 1024
#define ND 512

// ---------------- scratch (device globals; 16B-aligned for cp.async) -------
static __device__ __align__(16) __half g_xh [(size_t)NB * NN * ND];
static __device__ __align__(16) __half g_xl [(size_t)NB * NN * ND];
static __device__ __align__(16) __half g_xTh[(size_t)NB * ND * NN];
static __device__ __align__(16) __half g_xTl[(size_t)NB * ND * NN];
static __device__ __align__(16) __half g_WTh[(size_t)NH * ND * ND];
static __device__ __align__(16) __half g_WTl[(size_t)NH * ND * ND];
static __device__ __align__(16) __half g_Yh [(size_t)NB * NH * NN * ND];
static __device__ __align__(16) __half g_Yl [(size_t)NB * NH * NN * ND];
static __device__ __align__(16) float  g_S  [(size_t)NB * NH * NN * NN];
static __device__ __align__(16) __half g_Ph [(size_t)NB * NN * NN];
static __device__ __align__(16) __half g_Pl [(size_t)NB * NN * NN];

// ---------------- PTX helpers (base sm_103 features only) -------------------
__device__ __forceinline__ uint32_t smem_u32(const void* p) {
    uint32_t a;
    asm("{ .reg .u64 t; cvta.to.shared.u64 t, %1; cvt.u32.u64 %0, t; }" : "=r"(a) : "l"(p));
    return a;
}

#define CP_ASYNC16(dst, src) \
    asm volatile("cp.async.cg.shared.global [%0], [%1], 16;" :: "r"(dst), "l"(src))
#define CP_COMMIT()  asm volatile("cp.async.commit_group;" ::: "memory")
#define CP_WAIT0()   asm volatile("cp.async.wait_group 0;" ::: "memory")
#define CP_WAIT1()   asm volatile("cp.async.wait_group 1;" ::: "memory")

__device__ __forceinline__ void mma16816(float* c, const uint32_t* a, const uint32_t* b) {
    asm volatile(
        "mma.sync.aligned.m16n8k16.row.col.f32.f16.f16.f32 "
        "{%0,%1,%2,%3}, {%4,%5,%6,%7}, {%8,%9}, {%0,%1,%2,%3};"
        : "+f"(c[0]), "+f"(c[1]), "+f"(c[2]), "+f"(c[3])
        : "r"(a[0]), "r"(a[1]), "r"(a[2]), "r"(a[3]), "r"(b[0]), "r"(b[1]));
}

// ---------------- prep: split x -> (xh,xl) and transpose-split --------------
__global__ __launch_bounds__(256) void prep_x_kernel(const float* __restrict__ x) {
    __shared__ float ts[32][33];
    const int b = blockIdx.z, n0 = blockIdx.y * 32, d0 = blockIdx.x * 32;
    const int t = threadIdx.x;
    const int r = t >> 3, c0 = (t & 7) * 4;

    const float* src = x + ((size_t)b * NN + n0 + r) * ND + d0 + c0;
    float4 v = *(const float4*)src;
    ts[r][c0 + 0] = v.x; ts[r][c0 + 1] = v.y; ts[r][c0 + 2] = v.z; ts[r][c0 + 3] = v.w;

    size_t o = ((size_t)b * NN + n0 + r) * ND + d0 + c0;
    float vv[4] = {v.x, v.y, v.z, v.w};
#pragma unroll
    for (int j = 0; j < 4; j++) {
        __half h = __float2half(vv[j]);
        g_xh[o + j] = h;
        g_xl[o + j] = __float2half(vv[j] - __half2float(h));
    }
    __syncthreads();
    size_t ot = ((size_t)b * ND + d0 + r) * NN + n0 + c0;
#pragma unroll
    for (int j = 0; j < 4; j++) {
        float w = ts[c0 + j][r];
        __half h = __float2half(w);
        g_xTh[ot + j] = h;
        g_xTl[ot + j] = __float2half(w - __half2float(h));
    }
}

__global__ __launch_bounds__(256) void prep_w_kernel(const float* __restrict__ W) {
    __shared__ float ts[32][33];
    const int h = blockIdx.z, d0 = blockIdx.y * 32, e0 = blockIdx.x * 32;
    const int t = threadIdx.x;
    const int r = t >> 3, c0 = (t & 7) * 4;

    const float* src = W + ((size_t)h * ND + d0 + r) * ND + e0 + c0;
    float4 v = *(const float4*)src;
    ts[r][c0 + 0] = v.x; ts[r][c0 + 1] = v.y; ts[r][c0 + 2] = v.z; ts[r][c0 + 3] = v.w;
    __syncthreads();
    size_t ot = ((size_t)h * ND + e0 + r) * ND + d0 + c0;
#pragma unroll
    for (int j = 0; j < 4; j++) {
        float w = ts[c0 + j][r];
        __half hh = __float2half(w);
        g_WTh[ot + j] = hh;
        g_WTl[ot + j] = __float2half(w - __half2float(hh));
    }
}

// ---------------- mma.sync fp16x3 GEMM: D = A * B^T ------------------------
// 128x128 block tile, BK=32 halves, 8 warps (2M x 4N), 64x32 per warp.
// smem tiles: 128 rows x 40 halves (80B stride: 16B-aligned, conflict-free).
// MODE 0: Y(split) = scale * x @ W      (K=512)
// MODE 1: S = Ys @ x^T                  (K=512)
// MODE 2: out = P @ x                   (K=1024)
static constexpr int ROW_H = 40;                    // halves per smem row
static constexpr int TILE_BYTES = 128 * ROW_H * 2;  // 10240
static constexpr int OFF_AH = 0;
static constexpr int OFF_AL = TILE_BYTES;
static constexpr int OFF_BH = 2 * TILE_BYTES;
static constexpr int OFF_BL = 3 * TILE_BYTES;
static constexpr int STAGE_BYTES = 4 * TILE_BYTES;  // 40960
static constexpr int GEMM_SMEM = 2 * STAGE_BYTES;   // 81920

template <int MODE>
__global__ __launch_bounds__(256) void gemm_hmma_kernel(float* __restrict__ out) {
    extern __shared__ __align__(16) char dyn_smem[];

    const int t = threadIdx.x;
    const int wid = t >> 5, lane = t & 31;
    const int z = blockIdx.z;
    const int mBase = blockIdx.y * 128;
    const int nBase = blockIdx.x * 128;

    const __half *Ah, *Al, *Bh, *Bl;
    float* Cf = nullptr;
    __half *Ch = nullptr, *Cl = nullptr;
    int lda, ldb, ldc, nch;
    float alpha = 1.0f;

    if (MODE == 0) {
        const int b = z >> 2, h = z & 3;
        Ah = g_xh + (size_t)b * NN * ND;  Al = g_xl + (size_t)b * NN * ND;
        Bh = g_WTh + (size_t)h * ND * ND; Bl = g_WTl + (size_t)h * ND * ND;
        Ch = g_Yh + (size_t)z * NN * ND;  Cl = g_Yl + (size_t)z * NN * ND;
        lda = ND; ldb = ND; ldc = ND; nch = ND / 32;
        alpha = 0.04419417382415922f;   // 512^-0.5 folded into Y
    } else if (MODE == 1) {
        const int b = z >> 2;
        Ah = g_Yh + (size_t)z * NN * ND; Al = g_Yl + (size_t)z * NN * ND;
        Bh = g_xh + (size_t)b * NN * ND; Bl = g_xl + (size_t)b * NN * ND;
        Cf = g_S + (size_t)z * NN * NN;
        lda = ND; ldb = ND; ldc = NN; nch = ND / 32;
    } else {
        Ah = g_Ph + (size_t)z * NN * NN;  Al = g_Pl + (size_t)z * NN * NN;
        Bh = g_xTh + (size_t)z * ND * NN; Bl = g_xTl + (size_t)z * ND * NN;
        Cf = out + (size_t)z * NN * ND;
        lda = NN; ldb = NN; ldc = ND; nch = NN / 32;
    }

    const uint32_t dsb = smem_u32(dyn_smem);

    // stage loader: 4 tiles (Ah, Al, Bh, Bl), each 128 rows x 32 halves (64B)
    auto load_stage = [&](int kc, uint32_t sb) {
        const int kOff = kc * 32;
#pragma unroll
        for (int i = 0; i < 2; i++) {
            const int u = t * 2 + i;
            const int row = u >> 2, cb = u & 3;
            const uint32_t d = (uint32_t)(row * (ROW_H * 2) + cb * 16);
            const size_t ao = (size_t)(mBase + row) * lda + kOff + cb * 8;
            const size_t bo = (size_t)(nBase + row) * ldb + kOff + cb * 8;
            CP_ASYNC16(sb + OFF_AH + d, Ah + ao);
            CP_ASYNC16(sb + OFF_AL + d, Al + ao);
            CP_ASYNC16(sb + OFF_BH + d, Bh + bo);
            CP_ASYNC16(sb + OFF_BL + d, Bl + bo);
        }
    };

    // warp tiling: wm in {0,1} (64 rows), wn in {0..3} (32 cols)
    const int wm = wid & 1, wn = wid >> 1;

    float acc[4][4][4];
#pragma unroll
    for (int mt = 0; mt < 4; mt++)
#pragma unroll
        for (int nt = 0; nt < 4; nt++)
#pragma unroll
            for (int j = 0; j < 4; j++) acc[mt][nt][j] = 0.0f;

    load_stage(0, dsb);
    CP_COMMIT();

    for (int kc = 0; kc < nch; kc++) {
        if (kc + 1 < nch) {
            load_stage(kc + 1, dsb + (uint32_t)((kc + 1) & 1) * STAGE_BYTES);
            CP_COMMIT();
            CP_WAIT1();
        } else {
            CP_WAIT0();
        }
        __syncthreads();

        const char* sb = dyn_smem + (size_t)(kc & 1) * STAGE_BYTES;
        const __half* sAh = (const __half*)(sb + OFF_AH);
        const __half* sAl = (const __half*)(sb + OFF_AL);
        const __half* sBh = (const __half*)(sb + OFF_BH);
        const __half* sBl = (const __half*)(sb + OFF_BL);

#pragma unroll
        for (int k16 = 0; k16 < 32; k16 += 16) {
            const int c = k16 + (lane & 3) * 2;
            uint32_t fAh[4][4], fAl[4][4], fBh[4][2], fBl[4][2];
#pragma unroll
            for (int mt = 0; mt < 4; mt++) {
                const int r = wm * 64 + mt * 16 + (lane >> 2);
                fAh[mt][0] = *(const uint32_t*)(sAh + r * ROW_H + c);
                fAh[mt][1] = *(const uint32_t*)(sAh + (r + 8) * ROW_H + c);
                fAh[mt][2] = *(const uint32_t*)(sAh + r * ROW_H + c + 8);
                fAh[mt][3] = *(const uint32_t*)(sAh + (r + 8) * ROW_H + c + 8);
                fAl[mt][0] = *(const uint32_t*)(sAl + r * ROW_H + c);
                fAl[mt][1] = *(const uint32_t*)(sAl + (r + 8) * ROW_H + c);
                fAl[mt][2] = *(const uint32_t*)(sAl + r * ROW_H + c + 8);
                fAl[mt][3] = *(const uint32_t*)(sAl + (r + 8) * ROW_H + c + 8);
            }
#pragma unroll
            for (int nt = 0; nt < 4; nt++) {
                const int n = wn * 32 + nt * 8 + (lane >> 2);
                fBh[nt][0] = *(const uint32_t*)(sBh + n * ROW_H + c);
                fBh[nt][1] = *(const uint32_t*)(sBh + n * ROW_H + c + 8);
                fBl[nt][0] = *(const uint32_t*)(sBl + n * ROW_H + c);
                fBl[nt][1] = *(const uint32_t*)(sBl + n * ROW_H + c + 8);
            }
#pragma unroll
            for (int mt = 0; mt < 4; mt++)
#pragma unroll
                for (int nt = 0; nt < 4; nt++) {
                    mma16816(acc[mt][nt], fAh[mt], fBh[nt]);
                    mma16816(acc[mt][nt], fAh[mt], fBl[nt]);
                    mma16816(acc[mt][nt], fAl[mt], fBh[nt]);
                }
        }
        __syncthreads();
    }

    // epilogue
#pragma unroll
    for (int mt = 0; mt < 4; mt++) {
        const int r0 = mBase + wm * 64 + mt * 16 + (lane >> 2);
#pragma unroll
        for (int nt = 0; nt < 4; nt++) {
            const int c0 = nBase + wn * 32 + nt * 8 + (lane & 3) * 2;
            float v0 = acc[mt][nt][0] * alpha;
            float v1 = acc[mt][nt][1] * alpha;
            float v2 = acc[mt][nt][2] * alpha;
            float v3 = acc[mt][nt][3] * alpha;
            if (MODE == 0) {
                size_t o0 = (size_t)r0 * ldc + c0;
                size_t o1 = (size_t)(r0 + 8) * ldc + c0;
                __half h;
                h = __float2half(v0); Ch[o0] = h;     Cl[o0] = __float2half(v0 - __half2float(h));
                h = __float2half(v1); Ch[o0 + 1] = h; Cl[o0 + 1] = __float2half(v1 - __half2float(h));
                h = __float2half(v2); Ch[o1] = h;     Cl[o1] = __float2half(v2 - __half2float(h));
                h = __float2half(v3); Ch[o1 + 1] = h; Cl[o1 + 1] = __float2half(v3 - __half2float(h));
            } else {
                *(float2*)(Cf + (size_t)r0 * ldc + c0) = make_float2(v0, v1);
                *(float2*)(Cf + (size_t)(r0 + 8) * ldc + c0) = make_float2(v2, v3);
            }
        }
    }
}

// ---------------- K3: head-avg softmax -> split fp16 P ---------------------
__global__ __launch_bounds__(256) void softmax_avg_kernel() {
    const int bn = blockIdx.x;
    const int b = bn >> 10;
    const int n = bn & (NN - 1);
    const int t = threadIdx.x;
    const int lane = t & 31;
    const int warp = t >> 5;

    __shared__ float sred[8];
    __shared__ float sval;

    float a0 = 0.f, a1 = 0.f, a2 = 0.f, a3 = 0.f;

#pragma unroll
    for (int h = 0; h < NH; h++) {
        const float* row = g_S + ((size_t)(b * NH + h) * NN + n) * NN;
        float4 v = *(const float4*)(row + t * 4);

        float m = fmaxf(fmaxf(v.x, v.y), fmaxf(v.z, v.w));
#pragma unroll
        for (int o = 16; o; o >>= 1) m = fmaxf(m, __shfl_xor_sync(0xffffffffu, m, o));
        if (lane == 0) sred[warp] = m;
        __syncthreads();
        if (t == 0) {
            float mm = sred[0];
#pragma unroll
            for (int i = 1; i < 8; i++) mm = fmaxf(mm, sred[i]);
            sval = mm;
        }
        __syncthreads();
        m = sval;

        float e0 = expf(v.x - m), e1 = expf(v.y - m), e2 = expf(v.z - m), e3 = expf(v.w - m);
        float s = (e0 + e1) + (e2 + e3);
#pragma unroll
        for (int o = 16; o; o >>= 1) s += __shfl_xor_sync(0xffffffffu, s, o);
        if (lane == 0) sred[warp] = s;
        __syncthreads();
        if (t == 0) {
            float ss = 0.f;
#pragma unroll
            for (int i = 0; i < 8; i++) ss += sred[i];
            sval = ss;
        }
        __syncthreads();
        const float inv = 0.25f / sval;   // fold mean over heads

        a0 = fmaf(e0, inv, a0);
        a1 = fmaf(e1, inv, a1);
        a2 = fmaf(e2, inv, a2);
        a3 = fmaf(e3, inv, a3);
    }

    const size_t o = ((size_t)b * NN + n) * NN + t * 4;
    float av[4] = {a0, a1, a2, a3};
#pragma unroll
    for (int j = 0; j < 4; j++) {
        __half h = __float2half(av[j]);
        g_Ph[o + j] = h;
        g_Pl[o + j] = __float2half(av[j] - __half2float(h));
    }
}

// ---------------------------------------------------------------------------
extern "C" void kernel_launch(void* const* d_in, const int* in_sizes, int n_in,
                              void* d_out, int out_size) {
    const float* x = (const float*)d_in[0];   // [8, 1024, 512]
    const float* W = (const float*)d_in[1];   // [4, 512, 512]
    float* out = (float*)d_out;               // [8, 1024, 512]
    (void)in_sizes; (void)n_in; (void)out_size;

    cudaFuncSetAttribute(gemm_hmma_kernel<0>, cudaFuncAttributeMaxDynamicSharedMemorySize, GEMM_SMEM);
    cudaFuncSetAttribute(gemm_hmma_kernel<1>, cudaFuncAttributeMaxDynamicSharedMemorySize, GEMM_SMEM);
    cudaFuncSetAttribute(gemm_hmma_kernel<2>, cudaFuncAttributeMaxDynamicSharedMemorySize, GEMM_SMEM);

    prep_x_kernel<<<dim3(ND / 32, NN / 32, NB), 256>>>(x);
    prep_w_kernel<<<dim3(ND / 32, ND / 32, NH), 256>>>(W);

    // G1: Y(split) = scale * x @ W
    gemm_hmma_kernel<0><<<dim3(ND / 128, NN / 128, NB * NH), 256, GEMM_SMEM>>>(out);
    // G2: S = Ys @ x^T
    gemm_hmma_kernel<1><<<dim3(NN / 128, NN / 128, NB * NH), 256, GEMM_SMEM>>>(out);
    // K3: P(split) = mean_h softmax(S)
    softmax_avg_kernel<<<NB * NN, 256>>>();
    // G3: out = P @ x
    gemm_hmma_kernel<2><<<dim3(ND / 128, NN / 128, NB), 256, GEMM_SMEM>>>(out);
}